// round 9
// baseline (speedup 1.0000x reference)
#include <cuda_runtime.h>

// ---------------------------------------------------------------------------
// QuantumHybridHead: 4-qubit statevector sim, B=524288 samples.
//
// Math reduction:
//   encoder = per-qubit single rotation on |0>  -> product state (w2 = global
//   phase, dropped). First 12 trainable rotations fold into shared 2x2 M_q =
//   RZ*RY*RX (prep kernel). Qubit2 per-sample vector is a shared constant
//   column of M2. CNOTs = compile-time index permutation. Final RX(theta_q)
//   folds into observable: <Z>_post = cos(t)<Z>_pre + sin(t)<Y>_pre.
// ---------------------------------------------------------------------------

struct QConsts {
    float2 M0[2][2];   // qubit0: RZ*RY*RX(theta[0..2])
    float2 M1[2][2];   // qubit1
    float2 M3[2][2];   // qubit3
    float2 v2[2];      // qubit2: column 0 of M2 (its encoder RZ is global phase)
    float  cf[4];      // cos(theta[12+q])
    float  sf[4];      // sin(theta[12+q])
};
__device__ QConsts g_qc;

__device__ __forceinline__ float2 cmul(float2 a, float2 b) {
    return make_float2(fmaf(a.x, b.x, -(a.y * b.y)),
                       fmaf(a.x, b.y,  (a.y * b.x)));
}
__device__ __forceinline__ float2 cadd(float2 a, float2 b) {
    return make_float2(a.x + b.x, a.y + b.y);
}

// ------------------------- prep: theta -> constants -------------------------
__global__ void qprep(const float* __restrict__ theta) {
    if (threadIdx.x != 0 || blockIdx.x != 0) return;
#pragma unroll
    for (int q = 0; q < 4; q++) {
        float sa, ca, sb, cb, sc, cc;
        sincosf(theta[3*q + 0] * 0.5f, &sa, &ca);   // RX angle
        sincosf(theta[3*q + 1] * 0.5f, &sb, &cb);   // RY angle
        sincosf(theta[3*q + 2] * 0.5f, &sc, &cc);   // RZ angle

        float2 RX[2][2] = {
            { make_float2(ca, 0.f),  make_float2(0.f, -sa) },
            { make_float2(0.f, -sa), make_float2(ca, 0.f)  } };
        float2 RY[2][2] = {
            { make_float2(cb, 0.f),  make_float2(-sb, 0.f) },
            { make_float2(sb, 0.f),  make_float2(cb, 0.f)  } };
        float2 RZ[2][2] = {
            { make_float2(cc, -sc),  make_float2(0.f, 0.f) },
            { make_float2(0.f, 0.f), make_float2(cc, sc)   } };

        float2 T[2][2], M[2][2];
#pragma unroll
        for (int i = 0; i < 2; i++)
#pragma unroll
            for (int j = 0; j < 2; j++)
                T[i][j] = cadd(cmul(RY[i][0], RX[0][j]), cmul(RY[i][1], RX[1][j]));
#pragma unroll
        for (int i = 0; i < 2; i++)
#pragma unroll
            for (int j = 0; j < 2; j++)
                M[i][j] = cadd(cmul(RZ[i][0], T[0][j]), cmul(RZ[i][1], T[1][j]));

        if (q == 0) {
#pragma unroll
            for (int i = 0; i < 2; i++) { g_qc.M0[i][0] = M[i][0]; g_qc.M0[i][1] = M[i][1]; }
        } else if (q == 1) {
#pragma unroll
            for (int i = 0; i < 2; i++) { g_qc.M1[i][0] = M[i][0]; g_qc.M1[i][1] = M[i][1]; }
        } else if (q == 2) {
#pragma unroll
            for (int i = 0; i < 2; i++) { g_qc.v2[i] = M[i][0]; }
        } else {
#pragma unroll
            for (int i = 0; i < 2; i++) { g_qc.M3[i][0] = M[i][0]; g_qc.M3[i][1] = M[i][1]; }
        }
    }
#pragma unroll
    for (int q = 0; q < 4; q++) {
        float s, c;
        sincosf(theta[12 + q], &s, &c);   // full angle: RX' Z RX = cos(t) Z + sin(t) Y
        g_qc.cf[q] = c;
        g_qc.sf[q] = s;
    }
}

// CNOT(C,T): new[j] = old[j ^ (bit_C(j) << shift_T)] — pure register swaps.
// wire w -> bit shift (3-w)  (wire0 = MSB, matching reference reshape order).
template <int C, int T>
__device__ __forceinline__ void cnot_gate(float2* a) {
#pragma unroll
    for (int j = 0; j < 16; j++) {
        if (((j >> (3 - C)) & 1) && !((j >> (3 - T)) & 1)) {
            int k = j ^ (1 << (3 - T));
            float2 tmp = a[j]; a[j] = a[k]; a[k] = tmp;
        }
    }
}

// ------------------------------ main kernel --------------------------------
__global__ void __launch_bounds__(256)
qmain(const float4* __restrict__ in, float4* __restrict__ out, int B) {
    int b = blockIdx.x * blockDim.x + threadIdx.x;
    if (b >= B) return;

    float4 w = in[b];
    float s0, c0, s1, c1, s3, c3;
    __sincosf(w.x * 0.5f, &s0, &c0);
    __sincosf(w.y * 0.5f, &s1, &c1);
    __sincosf(w.w * 0.5f, &s3, &c3);
    // w.z (qubit2 RZ on |0>) is a global phase -> dropped.

    // per-qubit 2-vectors: v_q = M_q * (encoder_q |0>)
    //   e0 = (c0, -i s0) ;  e1 = (c1, s1) real ;  e3 = (c3, -i s3)
    float2 v0[2], v1[2], v3[2], vv2[2];
#pragma unroll
    for (int i = 0; i < 2; i++) {
        float2 A0 = g_qc.M0[i][0], A1 = g_qc.M0[i][1];
        v0[i] = make_float2(fmaf(A0.x, c0,  A1.y * s0),
                            fmaf(A0.y, c0, -(A1.x * s0)));
        float2 B0 = g_qc.M1[i][0], B1 = g_qc.M1[i][1];
        v1[i] = make_float2(fmaf(B0.x, c1,  B1.x * s1),
                            fmaf(B0.y, c1,  B1.y * s1));
        float2 D0 = g_qc.M3[i][0], D1 = g_qc.M3[i][1];
        v3[i] = make_float2(fmaf(D0.x, c3,  D1.y * s3),
                            fmaf(D0.y, c3, -(D1.x * s3)));
        vv2[i] = g_qc.v2[i];
    }

    // product state a[i0*8 + i1*4 + i2*2 + i3]
    float2 t01[4], t23[4];
#pragma unroll
    for (int i0 = 0; i0 < 2; i0++)
#pragma unroll
        for (int i1 = 0; i1 < 2; i1++)
            t01[i0 * 2 + i1] = cmul(v0[i0], v1[i1]);
#pragma unroll
    for (int i2 = 0; i2 < 2; i2++)
#pragma unroll
        for (int i3 = 0; i3 < 2; i3++)
            t23[i2 * 2 + i3] = cmul(vv2[i2], v3[i3]);

    float2 a[16];
#pragma unroll
    for (int j = 0; j < 16; j++)
        a[j] = cmul(t01[j >> 2], t23[j & 3]);

    // CNOT ladder (0,1) (1,2) (2,3) (3,0) — compile-time permutation
    cnot_gate<0, 1>(a);
    cnot_gate<1, 2>(a);
    cnot_gate<2, 3>(a);
    cnot_gate<3, 0>(a);

    // probabilities
    float p[16];
#pragma unroll
    for (int j = 0; j < 16; j++)
        p[j] = fmaf(a[j].x, a[j].x, a[j].y * a[j].y);

    // E_q = cos(t_q) <Z_q> + sin(t_q) <Y_q>,  <Y_q> = 2 * sum Im(conj(a0)*a1)
    float E[4];
#pragma unroll
    for (int q = 0; q < 4; q++) {
        const int mask = 1 << (3 - q);
        float Z = 0.f, Y = 0.f;
#pragma unroll
        for (int j = 0; j < 16; j++) {
            if (j & mask) continue;
            const int k = j | mask;
            Z += p[j] - p[k];
            Y = fmaf(a[j].x, a[k].y, Y);
            Y = fmaf(-a[j].y, a[k].x, Y);
        }
        E[q] = fmaf(g_qc.cf[q], Z, 2.f * g_qc.sf[q] * Y);
    }

    out[b] = make_float4(E[0], E[1], E[2], E[3]);
}

// ------------------------------ launch --------------------------------------
extern "C" void kernel_launch(void* const* d_in, const int* in_sizes, int n_in,
                              void* d_out, int out_size) {
    const float* inputs = (const float*)d_in[0];
    const float* theta  = (const float*)d_in[1];
    int in0 = in_sizes[0];
    if (in0 == 16) {  // defensive: metadata order swapped
        const float* t = inputs; inputs = theta; theta = t;
        in0 = in_sizes[1];
    }
    const int B = in0 / 4;

    qprep<<<1, 32>>>(theta);

    const int threads = 256;
    const int blocks  = (B + threads - 1) / threads;
    qmain<<<blocks, threads>>>((const float4*)inputs, (float4*)d_out, B);
}

// round 13
// speedup vs baseline: 1.0173x; 1.0173x over previous
#include <cuda_runtime.h>

// ---------------------------------------------------------------------------
// QuantumHybridHead: 4-qubit statevector sim, B=524288 samples.
//
// Math reduction:
//   encoder = per-qubit single rotation on |0>  -> product state (w2 = global
//   phase, dropped). First 12 trainable rotations fold into shared 2x2 M_q =
//   RZ*RY*RX (prep kernel). Qubit2 per-sample vector is a shared constant
//   column of M2. CNOTs = compile-time index permutation. Final RX(theta_q)
//   folds into observable: <Z>_post = cos(t)<Z>_pre + sin(t)<Y>_pre.
// ---------------------------------------------------------------------------

struct QConsts {
    float2 M0[2][2];   // qubit0: RZ*RY*RX(theta[0..2])
    float2 M1[2][2];   // qubit1
    float2 M3[2][2];   // qubit3
    float2 v2[2];      // qubit2: column 0 of M2 (its encoder RZ is global phase)
    float  cf[4];      // cos(theta[12+q])
    float  sf[4];      // sin(theta[12+q])
};
__device__ QConsts g_qc;

__device__ __forceinline__ float2 cmul(float2 a, float2 b) {
    return make_float2(fmaf(a.x, b.x, -(a.y * b.y)),
                       fmaf(a.x, b.y,  (a.y * b.x)));
}
__device__ __forceinline__ float2 cadd(float2 a, float2 b) {
    return make_float2(a.x + b.x, a.y + b.y);
}

// ------------------------- prep: theta -> constants -------------------------
__global__ void qprep(const float* __restrict__ theta) {
    if (threadIdx.x != 0 || blockIdx.x != 0) return;
#pragma unroll
    for (int q = 0; q < 4; q++) {
        float sa, ca, sb, cb, sc, cc;
        sincosf(theta[3*q + 0] * 0.5f, &sa, &ca);   // RX angle
        sincosf(theta[3*q + 1] * 0.5f, &sb, &cb);   // RY angle
        sincosf(theta[3*q + 2] * 0.5f, &sc, &cc);   // RZ angle

        float2 RX[2][2] = {
            { make_float2(ca, 0.f),  make_float2(0.f, -sa) },
            { make_float2(0.f, -sa), make_float2(ca, 0.f)  } };
        float2 RY[2][2] = {
            { make_float2(cb, 0.f),  make_float2(-sb, 0.f) },
            { make_float2(sb, 0.f),  make_float2(cb, 0.f)  } };
        float2 RZ[2][2] = {
            { make_float2(cc, -sc),  make_float2(0.f, 0.f) },
            { make_float2(0.f, 0.f), make_float2(cc, sc)   } };

        float2 T[2][2], M[2][2];
#pragma unroll
        for (int i = 0; i < 2; i++)
#pragma unroll
            for (int j = 0; j < 2; j++)
                T[i][j] = cadd(cmul(RY[i][0], RX[0][j]), cmul(RY[i][1], RX[1][j]));
#pragma unroll
        for (int i = 0; i < 2; i++)
#pragma unroll
            for (int j = 0; j < 2; j++)
                M[i][j] = cadd(cmul(RZ[i][0], T[0][j]), cmul(RZ[i][1], T[1][j]));

        if (q == 0) {
#pragma unroll
            for (int i = 0; i < 2; i++) { g_qc.M0[i][0] = M[i][0]; g_qc.M0[i][1] = M[i][1]; }
        } else if (q == 1) {
#pragma unroll
            for (int i = 0; i < 2; i++) { g_qc.M1[i][0] = M[i][0]; g_qc.M1[i][1] = M[i][1]; }
        } else if (q == 2) {
#pragma unroll
            for (int i = 0; i < 2; i++) { g_qc.v2[i] = M[i][0]; }
        } else {
#pragma unroll
            for (int i = 0; i < 2; i++) { g_qc.M3[i][0] = M[i][0]; g_qc.M3[i][1] = M[i][1]; }
        }
    }
#pragma unroll
    for (int q = 0; q < 4; q++) {
        float s, c;
        sincosf(theta[12 + q], &s, &c);   // full angle: RX' Z RX = cos(t) Z + sin(t) Y
        g_qc.cf[q] = c;
        g_qc.sf[q] = s;
    }
}

// CNOT(C,T): new[j] = old[j ^ (bit_C(j) << shift_T)] — pure register swaps.
// wire w -> bit shift (3-w)  (wire0 = MSB, matching reference reshape order).
template <int C, int T>
__device__ __forceinline__ void cnot_gate(float2* a) {
#pragma unroll
    for (int j = 0; j < 16; j++) {
        if (((j >> (3 - C)) & 1) && !((j >> (3 - T)) & 1)) {
            int k = j ^ (1 << (3 - T));
            float2 tmp = a[j]; a[j] = a[k]; a[k] = tmp;
        }
    }
}

// ------------------------------ main kernel --------------------------------
__global__ void __launch_bounds__(256)
qmain(const float4* __restrict__ in, float4* __restrict__ out, int B) {
    int b = blockIdx.x * blockDim.x + threadIdx.x;
    if (b >= B) return;

    float4 w = in[b];
    float s0, c0, s1, c1, s3, c3;
    __sincosf(w.x * 0.5f, &s0, &c0);
    __sincosf(w.y * 0.5f, &s1, &c1);
    __sincosf(w.w * 0.5f, &s3, &c3);
    // w.z (qubit2 RZ on |0>) is a global phase -> dropped.

    // per-qubit 2-vectors: v_q = M_q * (encoder_q |0>)
    //   e0 = (c0, -i s0) ;  e1 = (c1, s1) real ;  e3 = (c3, -i s3)
    float2 v0[2], v1[2], v3[2], vv2[2];
#pragma unroll
    for (int i = 0; i < 2; i++) {
        float2 A0 = g_qc.M0[i][0], A1 = g_qc.M0[i][1];
        v0[i] = make_float2(fmaf(A0.x, c0,  A1.y * s0),
                            fmaf(A0.y, c0, -(A1.x * s0)));
        float2 B0 = g_qc.M1[i][0], B1 = g_qc.M1[i][1];
        v1[i] = make_float2(fmaf(B0.x, c1,  B1.x * s1),
                            fmaf(B0.y, c1,  B1.y * s1));
        float2 D0 = g_qc.M3[i][0], D1 = g_qc.M3[i][1];
        v3[i] = make_float2(fmaf(D0.x, c3,  D1.y * s3),
                            fmaf(D0.y, c3, -(D1.x * s3)));
        vv2[i] = g_qc.v2[i];
    }

    // product state a[i0*8 + i1*4 + i2*2 + i3]
    float2 t01[4], t23[4];
#pragma unroll
    for (int i0 = 0; i0 < 2; i0++)
#pragma unroll
        for (int i1 = 0; i1 < 2; i1++)
            t01[i0 * 2 + i1] = cmul(v0[i0], v1[i1]);
#pragma unroll
    for (int i2 = 0; i2 < 2; i2++)
#pragma unroll
        for (int i3 = 0; i3 < 2; i3++)
            t23[i2 * 2 + i3] = cmul(vv2[i2], v3[i3]);

    float2 a[16];
#pragma unroll
    for (int j = 0; j < 16; j++)
        a[j] = cmul(t01[j >> 2], t23[j & 3]);

    // CNOT ladder (0,1) (1,2) (2,3) (3,0) — compile-time permutation
    cnot_gate<0, 1>(a);
    cnot_gate<1, 2>(a);
    cnot_gate<2, 3>(a);
    cnot_gate<3, 0>(a);

    // probabilities
    float p[16];
#pragma unroll
    for (int j = 0; j < 16; j++)
        p[j] = fmaf(a[j].x, a[j].x, a[j].y * a[j].y);

    // E_q = cos(t_q) <Z_q> + sin(t_q) <Y_q>,  <Y_q> = 2 * sum Im(conj(a0)*a1)
    float E[4];
#pragma unroll
    for (int q = 0; q < 4; q++) {
        const int mask = 1 << (3 - q);
        float Z = 0.f, Y = 0.f;
#pragma unroll
        for (int j = 0; j < 16; j++) {
            if (j & mask) continue;
            const int k = j | mask;
            Z += p[j] - p[k];
            Y = fmaf(a[j].x, a[k].y, Y);
            Y = fmaf(-a[j].y, a[k].x, Y);
        }
        E[q] = fmaf(g_qc.cf[q], Z, 2.f * g_qc.sf[q] * Y);
    }

    out[b] = make_float4(E[0], E[1], E[2], E[3]);
}

// ------------------------------ launch --------------------------------------
extern "C" void kernel_launch(void* const* d_in, const int* in_sizes, int n_in,
                              void* d_out, int out_size) {
    const float* inputs = (const float*)d_in[0];
    const float* theta  = (const float*)d_in[1];
    int in0 = in_sizes[0];
    if (in0 == 16) {  // defensive: metadata order swapped
        const float* t = inputs; inputs = theta; theta = t;
        in0 = in_sizes[1];
    }
    const int B = in0 / 4;

    qprep<<<1, 32>>>(theta);

    const int threads = 256;
    const int blocks  = (B + threads - 1) / threads;
    qmain<<<blocks, threads>>>((const float4*)inputs, (float4*)d_out, B);
}